// round 14
// baseline (speedup 1.0000x reference)
#include <cuda_runtime.h>
#include <cuda_fp16.h>
#include <math.h>
#include <stdint.h>

#define N_NODES 20000
#define N_EDGES 320000
#define F_IN 512
#define HEADS 8
#define DHEAD 64
#define HD 512
#define ALPHA_SLOPE 0.2f
#define EPS_DEN 1e-16f
#define NB_SCAN ((N_NODES + 255) / 256)   // 79

// ---------------- device scratch ----------------
__device__ uint4  g_pack[N_NODES * 128];            // {he[4] fp16, hr[4] fp16} per slot
__device__ __half g_xh[N_NODES * F_IN];             // fp16 X
__device__ __half g_wh[2 * HEADS * DHEAD * F_IN];   // fp16 W transposed [mat][h][d][f]
__device__ float  g_ssrc[N_NODES * HEADS];
__device__ float  g_sdst[N_NODES * HEADS];
__device__ int    g_cnt[N_NODES];
__device__ int    g_off[N_NODES + 1];
__device__ int    g_cur[N_NODES];
__device__ int    g_sorted[N_EDGES];
__device__ int    g_bsum[NB_SCAN];
__device__ int    g_is64;

#define N4X (N_NODES * F_IN / 4)          // 2,560,000

// ---------------- fused prep: zero cnt + detect dtype + X -> fp16 ----------------
__global__ void prep_kernel(const float4* __restrict__ x, const int* __restrict__ ei32) {
    int i = blockIdx.x * blockDim.x + threadIdx.x;
    if (i < N_NODES) g_cnt[i] = 0;
    if (i == 0) {
        int odd = 0;
        #pragma unroll 1
        for (int k = 0; k < 64; k++) odd |= ei32[2 * k + 1];
        g_is64 = (odd == 0) ? 1 : 0;
    }
    if (i < N4X) {
        float4 v = x[i];
        __half2 h0 = __floats2half2_rn(v.x, v.y);
        __half2 h1 = __floats2half2_rn(v.z, v.w);
        uint2 st;
        st.x = *(uint32_t*)&h0;
        st.y = *(uint32_t*)&h1;
        *(uint2*)((__half*)g_xh + (size_t)i * 4) = st;
    }
}

// transpose W: [h][f][d] f32 -> [mat][h][d][f] fp16
__global__ void transw_kernel(const float* __restrict__ We, const float* __restrict__ Wr) {
    __shared__ float sm[64][65];
    int bid = blockIdx.x;
    int fc = bid & 7;
    int h = (bid >> 3) & 7;
    int mat = bid >> 6;
    const float* W = (mat == 0) ? We : Wr;
    const float* base = W + (size_t)h * F_IN * DHEAD;
    int t = threadIdx.x;
    #pragma unroll
    for (int j = 0; j < 16; j++) {
        int idx = t + j * 256;
        int fi = idx >> 6, d = idx & 63;
        sm[fi][d] = base[(size_t)(fc * 64 + fi) * DHEAD + d];
    }
    __syncthreads();
    __half2* out = (__half2*)g_wh;
    #pragma unroll
    for (int j = 0; j < 8; j++) {
        int idx = t + j * 256;
        int d = idx >> 5;
        int fp = idx & 31;
        float v0 = sm[fp * 2][d];
        float v1 = sm[fp * 2 + 1][d];
        size_t o = (((size_t)(mat * 8 + h) * 64 + d) * F_IN + fc * 64 + fp * 2) >> 1;
        out[o] = __floats2half2_rn(v0, v1);
    }
}

__device__ __forceinline__ int load_edge(const void* ei, int idx) {
    int v;
    if (g_is64) v = (int)((const long long*)ei)[idx];
    else        v = ((const int*)ei)[idx];
    v = v < 0 ? 0 : (v >= N_NODES ? N_NODES - 1 : v);
    return v;
}

__global__ void hist_kernel(const void* __restrict__ ei) {
    int e = blockIdx.x * blockDim.x + threadIdx.x;
    if (e < N_EDGES) atomicAdd(&g_cnt[load_edge(ei, e)], 1);
}

// ---------------- 2-phase scan ----------------
__global__ void scan1_kernel() {
    __shared__ int ws[8];
    int t = threadIdx.x, lane = t & 31, w = t >> 5;
    int idx = blockIdx.x * 256 + t;
    int v = (idx < N_NODES) ? g_cnt[idx] : 0;
    int x = v;
    #pragma unroll
    for (int o = 16; o > 0; o >>= 1) x += __shfl_xor_sync(0xffffffffu, x, o);
    if (lane == 0) ws[w] = x;
    __syncthreads();
    if (t == 0) {
        int s = 0;
        #pragma unroll
        for (int i = 0; i < 8; i++) s += ws[i];
        g_bsum[blockIdx.x] = s;
    }
}

__global__ void scan2_kernel() {
    __shared__ int ws[8];
    __shared__ int pre;
    int t = threadIdx.x, lane = t & 31, w = t >> 5;
    int idx = blockIdx.x * 256 + t;
    if (t == 0) {
        int s = 0;
        #pragma unroll 1
        for (int i = 0; i < NB_SCAN; i++) {
            if (i == blockIdx.x) break;
            s += g_bsum[i];
        }
        pre = s;
    }
    int v = (idx < N_NODES) ? g_cnt[idx] : 0;
    int x = v;
    #pragma unroll
    for (int o = 1; o < 32; o <<= 1) {
        int y = __shfl_up_sync(0xffffffffu, x, o);
        if (lane >= o) x += y;
    }
    if (lane == 31) ws[w] = x;
    __syncthreads();
    if (t == 0) {
        int s = 0;
        #pragma unroll
        for (int i = 0; i < 8; i++) { int tmp = ws[i]; ws[i] = s; s += tmp; }
    }
    __syncthreads();
    int excl = pre + ws[w] + x - v;
    if (idx < N_NODES) { g_off[idx] = excl; g_cur[idx] = excl; }
    if (blockIdx.x == NB_SCAN - 1 && t == 255) g_off[N_NODES] = excl + v;
}

__global__ void scatter_kernel(const void* __restrict__ ei) {
    int e = blockIdx.x * blockDim.x + threadIdx.x;
    if (e < N_EDGES) {
        int s = load_edge(ei, e);
        int d = load_edge(ei, N_EDGES + e);
        int p = atomicAdd(&g_cur[s], 1);
        if (p >= 0 && p < N_EDGES) g_sorted[p] = d;
    }
}

// ---------------- fp16 tensor-core GEMM (m16n8k16, ldmatrix, 3-stage) ----------------
#define BM 256
#define BK 32
#define AS_H 40                         // fp16 stride (80B rows, conflict-free)
#define BS_H 40
#define A_HALFS (BM * AS_H)             // 10240
#define B_HALFS (64 * BS_H)             // 2560
#define BUF_HALFS (A_HALFS + B_HALFS)   // 12800 (25600 B)
#define NSTAGE 3

__device__ __forceinline__ void cp_async16(uint32_t saddr, const void* gaddr, int sz) {
    asm volatile("cp.async.cg.shared.global [%0], [%1], 16, %2;"
                 :: "r"(saddr), "l"(gaddr), "r"(sz));
}
__device__ __forceinline__ void ldsm_x4(uint32_t& r0, uint32_t& r1, uint32_t& r2, uint32_t& r3,
                                        uint32_t addr) {
    asm volatile("ldmatrix.sync.aligned.m8n8.x4.shared.b16 {%0,%1,%2,%3}, [%4];"
                 : "=r"(r0), "=r"(r1), "=r"(r2), "=r"(r3) : "r"(addr));
}

__global__ __launch_bounds__(128, 2)
void gemm_f16_kernel(const float* __restrict__ av) {
    extern __shared__ __half smh[];
    int tid = threadIdx.x;
    int wid = tid >> 5;
    int lane = tid & 31;
    int g = lane >> 2;
    int t4 = lane & 3;

    // ldmatrix lane addressing
    int rowA = lane & 15;
    int kA   = (lane >> 4) << 3;
    int colB = ((lane >> 4) << 3) + (lane & 7);
    int kB   = ((lane >> 3) & 1) << 3;

    int n0 = blockIdx.x * BM;
    int hy = blockIdx.y;          // 0..15
    int h = hy & 7;
    int mat = hy >> 3;            // 0=he, 1=hr

    const __half* X = g_xh;
    const __half* Wt = g_wh + (size_t)(mat * 8 + h) * 64 * F_IN;

    uint32_t sm_base = (uint32_t)__cvta_generic_to_shared(smh);

    float c[4][8][4];
    #pragma unroll
    for (int mi = 0; mi < 4; mi++)
        #pragma unroll
        for (int ni = 0; ni < 8; ni++)
            #pragma unroll
            for (int r = 0; r < 4; r++) c[mi][ni][r] = 0.f;

    auto issue = [&](int buf, int f0) {
        uint32_t abase = sm_base + (uint32_t)(buf * BUF_HALFS) * 2u;
        uint32_t bbase = abase + A_HALFS * 2u;
        #pragma unroll
        for (int j = 0; j < 8; j++) {
            int linear = tid + j * 128;
            int row = linear >> 2;
            int q = linear & 3;
            int grow = n0 + row;
            int pred = (grow < N_NODES) ? 16 : 0;
            int clamped = grow < N_NODES ? grow : (N_NODES - 1);
            const void* gp = X + (size_t)clamped * F_IN + f0 + q * 8;
            uint32_t sp = abase + (uint32_t)(row * AS_H + q * 8) * 2u;
            cp_async16(sp, gp, pred);
        }
        #pragma unroll
        for (int j = 0; j < 2; j++) {
            int linear = tid + j * 128;
            int d = linear >> 2;
            int q = linear & 3;
            const void* gp = Wt + (size_t)d * F_IN + f0 + q * 8;
            uint32_t sp = bbase + (uint32_t)(d * BS_H + q * 8) * 2u;
            cp_async16(sp, gp, 16);
        }
        asm volatile("cp.async.commit_group;");
    };

    const int TILES = F_IN / BK;   // 16
    issue(0, 0);
    issue(1, BK);

    for (int ti = 0; ti < TILES; ti++) {
        // prefetch chunk ti+2 (its buffer was last read by compute(ti-1),
        // protected by the end-of-iteration barrier below)
        if (ti + 2 < TILES) issue((ti + 2) % NSTAGE, (ti + 2) * BK);

        // wait until chunk ti is complete
        if (ti + 2 < TILES)      asm volatile("cp.async.wait_group 2;");
        else if (ti + 1 < TILES) asm volatile("cp.async.wait_group 1;");
        else                     asm volatile("cp.async.wait_group 0;");
        __syncthreads();

        uint32_t abyte = sm_base + (uint32_t)((ti % NSTAGE) * BUF_HALFS) * 2u;
        uint32_t bbyte = abyte + A_HALFS * 2u;

        #pragma unroll
        for (int ks = 0; ks < 2; ks++) {
            int k0 = ks * 16;
            uint32_t a[4][4], b[8][2];
            #pragma unroll
            for (int mi = 0; mi < 4; mi++) {
                uint32_t addr = abyte +
                    (uint32_t)((wid * 64 + mi * 16 + rowA) * AS_H + k0 + kA) * 2u;
                ldsm_x4(a[mi][0], a[mi][1], a[mi][2], a[mi][3], addr);
            }
            #pragma unroll
            for (int p = 0; p < 4; p++) {
                uint32_t addr = bbyte +
                    (uint32_t)((p * 16 + colB) * BS_H + k0 + kB) * 2u;
                ldsm_x4(b[2 * p][0], b[2 * p][1], b[2 * p + 1][0], b[2 * p + 1][1], addr);
            }
            #pragma unroll
            for (int mi = 0; mi < 4; mi++)
                #pragma unroll
                for (int ni = 0; ni < 8; ni++) {
                    asm volatile(
                        "mma.sync.aligned.m16n8k16.row.col.f32.f16.f16.f32 "
                        "{%0,%1,%2,%3}, {%4,%5,%6,%7}, {%8,%9}, {%0,%1,%2,%3};"
                        : "+f"(c[mi][ni][0]), "+f"(c[mi][ni][1]),
                          "+f"(c[mi][ni][2]), "+f"(c[mi][ni][3])
                        : "r"(a[mi][0]), "r"(a[mi][1]), "r"(a[mi][2]), "r"(a[mi][3]),
                          "r"(b[ni][0]), "r"(b[ni][1]));
                }
        }
        __syncthreads();
    }

    // ---- fused s-dots (mat==0): ssrc/sdst from fp32 accumulators ----
    if (mat == 0) {
        float as0[8], as1[8], ad0[8], ad1[8];
        #pragma unroll
        for (int ni = 0; ni < 8; ni++) {
            int d0 = ni * 8 + 2 * t4;
            as0[ni] = av[h * 320 + d0];
            as1[ni] = av[h * 320 + d0 + 1];
            ad0[ni] = av[h * 320 + 64 + d0];
            ad1[ni] = av[h * 320 + 64 + d0 + 1];
        }
        #pragma unroll
        for (int mi = 0; mi < 4; mi++) {
            float ps0 = 0.f, ps1 = 0.f, pd0 = 0.f, pd1 = 0.f;
            #pragma unroll
            for (int ni = 0; ni < 8; ni++) {
                ps0 += c[mi][ni][0] * as0[ni] + c[mi][ni][1] * as1[ni];
                ps1 += c[mi][ni][2] * as0[ni] + c[mi][ni][3] * as1[ni];
                pd0 += c[mi][ni][0] * ad0[ni] + c[mi][ni][1] * ad1[ni];
                pd1 += c[mi][ni][2] * ad0[ni] + c[mi][ni][3] * ad1[ni];
            }
            #pragma unroll
            for (int o = 1; o <= 2; o <<= 1) {
                ps0 += __shfl_xor_sync(0xffffffffu, ps0, o);
                ps1 += __shfl_xor_sync(0xffffffffu, ps1, o);
                pd0 += __shfl_xor_sync(0xffffffffu, pd0, o);
                pd1 += __shfl_xor_sync(0xffffffffu, pd1, o);
            }
            if (t4 == 0) {
                int r0 = n0 + wid * 64 + mi * 16 + g;
                if (r0 < N_NODES) {
                    g_ssrc[r0 * HEADS + h] = ps0;
                    g_sdst[r0 * HEADS + h] = pd0;
                }
                if (r0 + 8 < N_NODES) {
                    g_ssrc[(r0 + 8) * HEADS + h] = ps1;
                    g_sdst[(r0 + 8) * HEADS + h] = pd1;
                }
            }
        }
    }

    // ---- epilogue -> packed fp16 ----
    __half* packh = (__half*)g_pack;
    #pragma unroll
    for (int mi = 0; mi < 4; mi++) {
        int r0 = n0 + wid * 64 + mi * 16 + g;
        #pragma unroll
        for (int ni = 0; ni < 8; ni++) {
            int col = h * 64 + ni * 8 + 2 * t4;
            int slot = col >> 2;
            int sub = col & 3;
            size_t base0 = ((size_t)r0 * 128 + slot) * 8 + (size_t)mat * 4 + sub;
            size_t base1 = ((size_t)(r0 + 8) * 128 + slot) * 8 + (size_t)mat * 4 + sub;
            if (r0 < N_NODES)
                *(__half2*)(packh + base0) = __floats2half2_rn(c[mi][ni][0], c[mi][ni][1]);
            if (r0 + 8 < N_NODES)
                *(__half2*)(packh + base1) = __floats2half2_rn(c[mi][ni][2], c[mi][ni][3]);
        }
    }
}

// ---------------- helpers ----------------
__device__ __forceinline__ float4 h4_to_f4(uint32_t lo, uint32_t hi) {
    float2 f0 = __half22float2(*(__half2*)&lo);
    float2 f1 = __half22float2(*(__half2*)&hi);
    return make_float4(f0.x, f0.y, f1.x, f1.y);
}

// ---------------- attention (no-max softmax, 4x unrolled, packed fp16) ----------------
__global__ __launch_bounds__(128)
void attn_kernel(const float* __restrict__ a, float* __restrict__ out) {
    int n = blockIdx.x;
    int t = threadIdx.x;
    int h = t >> 4;
    int l = t & 15;

    int e0 = g_off[n];
    int e1 = g_off[n + 1];

    uint4 own = g_pack[(size_t)n * 128 + t];
    float4 hrs = h4_to_f4(own.z, own.w);
    float4 adif = *(const float4*)(a + h * 320 + 128 + l * 4);
    float4 aabs = *(const float4*)(a + h * 320 + 192 + l * 4);
    float4 aprd = *(const float4*)(a + h * 320 + 256 + l * 4);
    float ss = g_ssrc[n * HEADS + h];

    float denom = 0.f;
    float4 acc = make_float4(0.f, 0.f, 0.f, 0.f);

    int i = e0;
    for (; i + 4 <= e1; i += 4) {
        int d0 = g_sorted[i];
        int d1 = g_sorted[i + 1];
        int d2 = g_sorted[i + 2];
        int d3 = g_sorted[i + 3];

        uint4 pk0 = g_pack[(size_t)d0 * 128 + t];
        uint4 pk1 = g_pack[(size_t)d1 * 128 + t];
        uint4 pk2 = g_pack[(size_t)d2 * 128 + t];
        uint4 pk3 = g_pack[(size_t)d3 * 128 + t];
        float sd0 = g_sdst[d0 * HEADS + h];
        float sd1 = g_sdst[d1 * HEADS + h];
        float sd2 = g_sdst[d2 * HEADS + h];
        float sd3 = g_sdst[d3 * HEADS + h];

        float4 he0 = h4_to_f4(pk0.x, pk0.y);
        float4 r0  = h4_to_f4(pk0.z, pk0.w);
        float4 he1 = h4_to_f4(pk1.x, pk1.y);
        float4 r1  = h4_to_f4(pk1.z, pk1.w);
        float4 he2 = h4_to_f4(pk2.x, pk2.y);
        float4 r2  = h4_to_f4(pk2.z, pk2.w);
        float4 he3 = h4_to_f4(pk3.x, pk3.y);
        float4 r3  = h4_to_f4(pk3.z, pk3.w);

        float p0, p1, p2, p3;
        {
            float dx = r0.x - hrs.x, dy = r0.y - hrs.y, dz = r0.z - hrs.z, dw = r0.w - hrs.w;
            p0  = dx * adif.x + fabsf(dx) * aabs.x + hrs.x * r0.x * aprd.x;
            p0 += dy * adif.y + fabsf(dy) * aabs.y + hrs.y * r0.y * aprd.y;
            p0 += dz * adif.z + fabsf(dz) * aabs.z + hrs.z * r0.z * aprd.z;
            p0 += dw * adif.w + fabsf(dw) * aabs.w + hrs.w * r0.w * aprd.w;
        }
        {
            float dx = r1.x - hrs.x, dy = r1.y - hrs.y, dz = r1.z - hrs.z, dw = r1.w - hrs.w;
            p1  = dx * adif.x + fabsf(dx) * aabs.x + hrs.x * r1.x * aprd.x;
            p1 += dy * adif.y + fabsf(dy) * aabs.y + hrs.y * r1.y * aprd.y;
            p1 += dz * adif.z + fabsf(dz) * aabs.z + hrs.z * r1.z * aprd.z;
            p1 += dw * adif.w + fabsf(dw) * aabs.w + hrs.w * r1.w * aprd.w;
        }
        {
            float dx = r2.x - hrs.x, dy = r2.y - hrs.y, dz = r2.z - hrs.z, dw = r2.w - hrs.w;
            p2  = dx * adif.x + fabsf(dx) * aabs.x + hrs.x * r2.x * aprd.x;
            p2 += dy * adif.y + fabsf(dy) * aabs.y + hrs.y * r2.y * aprd.y;
            p2 += dz * adif.z + fabsf(dz) * aabs.z + hrs.z * r2.z * aprd.z;
            p2 += dw * adif.w + fabsf(dw) * aabs.w + hrs.w * r2.w * aprd.w;
        }
        {
            float dx = r3.x - hrs.x, dy = r3.y - hrs.y, dz = r3.z - hrs.z, dw = r3.w - hrs.w;
            p3  = dx * adif.x + fabsf(dx) * aabs.x + hrs.x * r3.x * aprd.x;
            p3 += dy * adif.y + fabsf(dy) * aabs.y + hrs.y * r3.y * aprd.y;
            p3 += dz * adif.z + fabsf(dz) * aabs.z + hrs.z * r3.z * aprd.z;
            p3 += dw * adif.w + fabsf(dw) * aabs.w + hrs.w * r3.w * aprd.w;
        }
        #pragma unroll
        for (int o = 8; o > 0; o >>= 1) {
            p0 += __shfl_xor_sync(0xffffffffu, p0, o);
            p1 += __shfl_xor_sync(0xffffffffu, p1, o);
            p2 += __shfl_xor_sync(0xffffffffu, p2, o);
            p3 += __shfl_xor_sync(0xffffffffu, p3, o);
        }

        float s0 = p0 + ss + sd0;
        float s1 = p1 + ss + sd1;
        float s2 = p2 + ss + sd2;
        float s3 = p3 + ss + sd3;
        float a0 = s0 > 0.f ? s0 : ALPHA_SLOPE * s0;
        float a1 = s1 > 0.f ? s1 : ALPHA_SLOPE * s1;
        float a2 = s2 > 0.f ? s2 : ALPHA_SLOPE * s2;
        float a3 = s3 > 0.f ? s3 : ALPHA_SLOPE * s3;
        float w0 = __expf(a0);
        float w1 = __expf(a1);
        float w2 = __expf(a2);
        float w3 = __expf(a3);

        acc.x += w0 * he0.x + w1 * he1.x + w2 * he2.x + w3 * he3.x;
        acc.y += w0 * he0.y + w1 * he1.y + w2 * he2.y + w3 * he3.y;
        acc.z += w0 * he0.z + w1 * he1.z + w2 * he2.z + w3 * he3.z;
        acc.w += w0 * he0.w + w1 * he1.w + w2 * he2.w + w3 * he3.w;
        denom += w0 + w1 + w2 + w3;
    }
    for (; i < e1; i++) {
        int d0 = g_sorted[i];
        uint4 pk0 = g_pack[(size_t)d0 * 128 + t];
        float sd0 = g_sdst[d0 * HEADS + h];
        float4 he0 = h4_to_f4(pk0.x, pk0.y);
        float4 r0  = h4_to_f4(pk0.z, pk0.w);
        float p0;
        float dx = r0.x - hrs.x, dy = r0.y - hrs.y, dz = r0.z - hrs.z, dw = r0.w - hrs.w;
        p0  = dx * adif.x + fabsf(dx) * aabs.x + hrs.x * r0.x * aprd.x;
        p0 += dy * adif.y + fabsf(dy) * aabs.y + hrs.y * r0.y * aprd.y;
        p0 += dz * adif.z + fabsf(dz) * aabs.z + hrs.z * r0.z * aprd.z;
        p0 += dw * adif.w + fabsf(dw) * aabs.w + hrs.w * r0.w * aprd.w;
        #pragma unroll
        for (int o = 8; o > 0; o >>= 1) p0 += __shfl_xor_sync(0xffffffffu, p0, o);
        float s0 = p0 + ss + sd0;
        float a0 = s0 > 0.f ? s0 : ALPHA_SLOPE * s0;
        float w0 = __expf(a0);
        acc.x += w0 * he0.x;
        acc.y += w0 * he0.y;
        acc.z += w0 * he0.z;
        acc.w += w0 * he0.w;
        denom += w0;
    }

    float inv = 1.f / (denom + EPS_DEN);
    float4 o4 = make_float4(acc.x * inv, acc.y * inv, acc.z * inv, acc.w * inv);
    *(float4*)(out + (size_t)n * HD + t * 4) = o4;
}

// ---------------- launch ----------------
extern "C" void kernel_launch(void* const* d_in, const int* in_sizes, int n_in,
                              void* d_out, int out_size) {
    const float* x = (const float*)d_in[0];
    const void* ei = d_in[1];
    const float* We = (const float*)d_in[2];
    const float* Wr = (const float*)d_in[3];
    const float* a = (const float*)d_in[4];
    float* out = (float*)d_out;

    prep_kernel<<<(N4X + 255) / 256, 256>>>((const float4*)x, (const int*)ei);
    transw_kernel<<<128, 256>>>(We, Wr);
    hist_kernel<<<(N_EDGES + 255) / 256, 256>>>(ei);

    size_t smem_bytes = NSTAGE * BUF_HALFS * sizeof(__half);   // 76800
    cudaFuncSetAttribute(gemm_f16_kernel, cudaFuncAttributeMaxDynamicSharedMemorySize, (int)smem_bytes);
    dim3 ggrid((N_NODES + BM - 1) / BM, 16);
    gemm_f16_kernel<<<ggrid, 128, smem_bytes>>>(a);

    scan1_kernel<<<NB_SCAN, 256>>>();
    scan2_kernel<<<NB_SCAN, 256>>>();
    scatter_kernel<<<(N_EDGES + 255) / 256, 256>>>(ei);

    attn_kernel<<<N_NODES, 128>>>(a, out);
}

// round 15
// speedup vs baseline: 1.0352x; 1.0352x over previous
#include <cuda_runtime.h>
#include <cuda_fp16.h>
#include <math.h>
#include <stdint.h>

#define N_NODES 20000
#define N_EDGES 320000
#define F_IN 512
#define HEADS 8
#define DHEAD 64
#define HD 512
#define ALPHA_SLOPE 0.2f
#define EPS_DEN 1e-16f
#define NB_SCAN ((N_NODES + 255) / 256)   // 79

// ---------------- device scratch ----------------
__device__ uint4  g_pack[N_NODES * 128];            // {he[4] fp16, hr[4] fp16} per slot
__device__ __half g_xh[N_NODES * F_IN];             // fp16 X
__device__ __half g_wh[2 * HEADS * DHEAD * F_IN];   // fp16 W transposed [mat][h][d][f]
__device__ float  g_ssrc[N_NODES * HEADS];
__device__ float  g_sdst[N_NODES * HEADS];
__device__ int    g_cnt[N_NODES];
__device__ int    g_off[N_NODES + 1];
__device__ int    g_cur[N_NODES];
__device__ int    g_sorted[N_EDGES];
__device__ int    g_bsum[NB_SCAN];
__device__ int    g_is64;

#define N4X (N_NODES * F_IN / 4)          // 2,560,000

// ---------------- fused prep: zero cnt + detect dtype + X -> fp16 ----------------
__global__ void prep_kernel(const float4* __restrict__ x, const int* __restrict__ ei32) {
    int i = blockIdx.x * blockDim.x + threadIdx.x;
    if (i < N_NODES) g_cnt[i] = 0;
    if (i == 0) {
        int odd = 0;
        #pragma unroll 1
        for (int k = 0; k < 64; k++) odd |= ei32[2 * k + 1];
        g_is64 = (odd == 0) ? 1 : 0;
    }
    if (i < N4X) {
        float4 v = x[i];
        __half2 h0 = __floats2half2_rn(v.x, v.y);
        __half2 h1 = __floats2half2_rn(v.z, v.w);
        uint2 st;
        st.x = *(uint32_t*)&h0;
        st.y = *(uint32_t*)&h1;
        *(uint2*)((__half*)g_xh + (size_t)i * 4) = st;
    }
}

// transpose W: [h][f][d] f32 -> [mat][h][d][f] fp16
__global__ void transw_kernel(const float* __restrict__ We, const float* __restrict__ Wr) {
    __shared__ float sm[64][65];
    int bid = blockIdx.x;
    int fc = bid & 7;
    int h = (bid >> 3) & 7;
    int mat = bid >> 6;
    const float* W = (mat == 0) ? We : Wr;
    const float* base = W + (size_t)h * F_IN * DHEAD;
    int t = threadIdx.x;
    #pragma unroll
    for (int j = 0; j < 16; j++) {
        int idx = t + j * 256;
        int fi = idx >> 6, d = idx & 63;
        sm[fi][d] = base[(size_t)(fc * 64 + fi) * DHEAD + d];
    }
    __syncthreads();
    __half2* out = (__half2*)g_wh;
    #pragma unroll
    for (int j = 0; j < 8; j++) {
        int idx = t + j * 256;
        int d = idx >> 5;
        int fp = idx & 31;
        float v0 = sm[fp * 2][d];
        float v1 = sm[fp * 2 + 1][d];
        size_t o = (((size_t)(mat * 8 + h) * 64 + d) * F_IN + fc * 64 + fp * 2) >> 1;
        out[o] = __floats2half2_rn(v0, v1);
    }
}

__device__ __forceinline__ int load_edge(const void* ei, int idx) {
    int v;
    if (g_is64) v = (int)((const long long*)ei)[idx];
    else        v = ((const int*)ei)[idx];
    v = v < 0 ? 0 : (v >= N_NODES ? N_NODES - 1 : v);
    return v;
}

__global__ void hist_kernel(const void* __restrict__ ei) {
    int e = blockIdx.x * blockDim.x + threadIdx.x;
    if (e < N_EDGES) atomicAdd(&g_cnt[load_edge(ei, e)], 1);
}

// ---------------- 2-phase scan ----------------
__global__ void scan1_kernel() {
    __shared__ int ws[8];
    int t = threadIdx.x, lane = t & 31, w = t >> 5;
    int idx = blockIdx.x * 256 + t;
    int v = (idx < N_NODES) ? g_cnt[idx] : 0;
    int x = v;
    #pragma unroll
    for (int o = 16; o > 0; o >>= 1) x += __shfl_xor_sync(0xffffffffu, x, o);
    if (lane == 0) ws[w] = x;
    __syncthreads();
    if (t == 0) {
        int s = 0;
        #pragma unroll
        for (int i = 0; i < 8; i++) s += ws[i];
        g_bsum[blockIdx.x] = s;
    }
}

__global__ void scan2_kernel() {
    __shared__ int ws[8];
    __shared__ int pre;
    int t = threadIdx.x, lane = t & 31, w = t >> 5;
    int idx = blockIdx.x * 256 + t;
    if (t == 0) {
        int s = 0;
        #pragma unroll 1
        for (int i = 0; i < NB_SCAN; i++) {
            if (i == blockIdx.x) break;
            s += g_bsum[i];
        }
        pre = s;
    }
    int v = (idx < N_NODES) ? g_cnt[idx] : 0;
    int x = v;
    #pragma unroll
    for (int o = 1; o < 32; o <<= 1) {
        int y = __shfl_up_sync(0xffffffffu, x, o);
        if (lane >= o) x += y;
    }
    if (lane == 31) ws[w] = x;
    __syncthreads();
    if (t == 0) {
        int s = 0;
        #pragma unroll
        for (int i = 0; i < 8; i++) { int tmp = ws[i]; ws[i] = s; s += tmp; }
    }
    __syncthreads();
    int excl = pre + ws[w] + x - v;
    if (idx < N_NODES) { g_off[idx] = excl; g_cur[idx] = excl; }
    if (blockIdx.x == NB_SCAN - 1 && t == 255) g_off[N_NODES] = excl + v;
}

__global__ void scatter_kernel(const void* __restrict__ ei) {
    int e = blockIdx.x * blockDim.x + threadIdx.x;
    if (e < N_EDGES) {
        int s = load_edge(ei, e);
        int d = load_edge(ei, N_EDGES + e);
        int p = atomicAdd(&g_cur[s], 1);
        if (p >= 0 && p < N_EDGES) g_sorted[p] = d;
    }
}

// ---------------- fp16 tensor-core GEMM (m16n8k16, ldmatrix, 3 CTAs/SM) ----------------
// block tile 128x64, BK=32; 4 warps of 32x64; grid (157, 16)
#define BM 128
#define BK 32
#define AS_H 40                         // fp16 stride (80B rows, conflict-free)
#define BS_H 40
#define A_HALFS (BM * AS_H)             // 5120
#define B_HALFS (64 * BS_H)             // 2560
#define BUF_HALFS (A_HALFS + B_HALFS)   // 7680 (15360 B)

__device__ __forceinline__ void cp_async16(uint32_t saddr, const void* gaddr, int sz) {
    asm volatile("cp.async.cg.shared.global [%0], [%1], 16, %2;"
                 :: "r"(saddr), "l"(gaddr), "r"(sz));
}
__device__ __forceinline__ void ldsm_x4(uint32_t& r0, uint32_t& r1, uint32_t& r2, uint32_t& r3,
                                        uint32_t addr) {
    asm volatile("ldmatrix.sync.aligned.m8n8.x4.shared.b16 {%0,%1,%2,%3}, [%4];"
                 : "=r"(r0), "=r"(r1), "=r"(r2), "=r"(r3) : "r"(addr));
}

__global__ __launch_bounds__(128, 3)
void gemm_f16_kernel(const float* __restrict__ av) {
    extern __shared__ __half smh[];
    int tid = threadIdx.x;
    int wid = tid >> 5;
    int lane = tid & 31;
    int g = lane >> 2;
    int t4 = lane & 3;

    // ldmatrix lane addressing
    int rowA = lane & 15;
    int kA   = (lane >> 4) << 3;
    int colB = ((lane >> 4) << 3) + (lane & 7);
    int kB   = ((lane >> 3) & 1) << 3;

    int n0 = blockIdx.x * BM;
    int hy = blockIdx.y;          // 0..15
    int h = hy & 7;
    int mat = hy >> 3;            // 0=he, 1=hr

    const __half* X = g_xh;
    const __half* Wt = g_wh + (size_t)(mat * 8 + h) * 64 * F_IN;

    uint32_t sm_base = (uint32_t)__cvta_generic_to_shared(smh);

    float c[2][8][4];
    #pragma unroll
    for (int mi = 0; mi < 2; mi++)
        #pragma unroll
        for (int ni = 0; ni < 8; ni++)
            #pragma unroll
            for (int r = 0; r < 4; r++) c[mi][ni][r] = 0.f;

    auto issue = [&](int buf, int f0) {
        uint32_t abase = sm_base + (uint32_t)(buf * BUF_HALFS) * 2u;
        uint32_t bbase = abase + A_HALFS * 2u;
        // A: 128 rows x 32 fp16 = 64B/row -> 512 x 16B ops, 4 per thread
        #pragma unroll
        for (int j = 0; j < 4; j++) {
            int linear = tid + j * 128;
            int row = linear >> 2;
            int q = linear & 3;
            int grow = n0 + row;
            int pred = (grow < N_NODES) ? 16 : 0;
            int clamped = grow < N_NODES ? grow : (N_NODES - 1);
            const void* gp = X + (size_t)clamped * F_IN + f0 + q * 8;
            uint32_t sp = abase + (uint32_t)(row * AS_H + q * 8) * 2u;
            cp_async16(sp, gp, pred);
        }
        // B: 64 d-rows x 32 fp16 -> 256 x 16B, 2 per thread
        #pragma unroll
        for (int j = 0; j < 2; j++) {
            int linear = tid + j * 128;
            int d = linear >> 2;
            int q = linear & 3;
            const void* gp = Wt + (size_t)d * F_IN + f0 + q * 8;
            uint32_t sp = bbase + (uint32_t)(d * BS_H + q * 8) * 2u;
            cp_async16(sp, gp, 16);
        }
        asm volatile("cp.async.commit_group;");
    };

    const int TILES = F_IN / BK;   // 16
    issue(0, 0);

    for (int ti = 0; ti < TILES; ti++) {
        if (ti + 1 < TILES) {
            issue((ti + 1) & 1, (ti + 1) * BK);
            asm volatile("cp.async.wait_group 1;");
        } else {
            asm volatile("cp.async.wait_group 0;");
        }
        __syncthreads();

        uint32_t abyte = sm_base + (uint32_t)((ti & 1) * BUF_HALFS) * 2u;
        uint32_t bbyte = abyte + A_HALFS * 2u;

        #pragma unroll
        for (int ks = 0; ks < 2; ks++) {
            int k0 = ks * 16;
            uint32_t a[2][4], b[8][2];
            #pragma unroll
            for (int mi = 0; mi < 2; mi++) {
                uint32_t addr = abyte +
                    (uint32_t)((wid * 32 + mi * 16 + rowA) * AS_H + k0 + kA) * 2u;
                ldsm_x4(a[mi][0], a[mi][1], a[mi][2], a[mi][3], addr);
            }
            #pragma unroll
            for (int p = 0; p < 4; p++) {
                uint32_t addr = bbyte +
                    (uint32_t)((p * 16 + colB) * BS_H + k0 + kB) * 2u;
                ldsm_x4(b[2 * p][0], b[2 * p][1], b[2 * p + 1][0], b[2 * p + 1][1], addr);
            }
            #pragma unroll
            for (int mi = 0; mi < 2; mi++)
                #pragma unroll
                for (int ni = 0; ni < 8; ni++) {
                    asm volatile(
                        "mma.sync.aligned.m16n8k16.row.col.f32.f16.f16.f32 "
                        "{%0,%1,%2,%3}, {%4,%5,%6,%7}, {%8,%9}, {%0,%1,%2,%3};"
                        : "+f"(c[mi][ni][0]), "+f"(c[mi][ni][1]),
                          "+f"(c[mi][ni][2]), "+f"(c[mi][ni][3])
                        : "r"(a[mi][0]), "r"(a[mi][1]), "r"(a[mi][2]), "r"(a[mi][3]),
                          "r"(b[ni][0]), "r"(b[ni][1]));
                }
        }
        __syncthreads();
    }

    // ---- fused s-dots (mat==0): ssrc/sdst from fp32 accumulators ----
    if (mat == 0) {
        float as0[8], as1[8], ad0[8], ad1[8];
        #pragma unroll
        for (int ni = 0; ni < 8; ni++) {
            int d0 = ni * 8 + 2 * t4;
            as0[ni] = av[h * 320 + d0];
            as1[ni] = av[h * 320 + d0 + 1];
            ad0[ni] = av[h * 320 + 64 + d0];
            ad1[ni] = av[h * 320 + 64 + d0 + 1];
        }
        #pragma unroll
        for (int mi = 0; mi < 2; mi++) {
            float ps0 = 0.f, ps1 = 0.f, pd0 = 0.f, pd1 = 0.f;
            #pragma unroll
            for (int ni = 0; ni < 8; ni++) {
                ps0 += c[mi][ni][0] * as0[ni] + c[mi][ni][1] * as1[ni];
                ps1 += c[mi][ni][2] * as0[ni] + c[mi][ni][3] * as1[ni];
                pd0 += c[mi][ni][0] * ad0[ni] + c[mi][ni][1] * ad1[ni];
                pd1 += c[mi][ni][2] * ad0[ni] + c[mi][ni][3] * ad1[ni];
            }
            #pragma unroll
            for (int o = 1; o <= 2; o <<= 1) {
                ps0 += __shfl_xor_sync(0xffffffffu, ps0, o);
                ps1 += __shfl_xor_sync(0xffffffffu, ps1, o);
                pd0 += __shfl_xor_sync(0xffffffffu, pd0, o);
                pd1 += __shfl_xor_sync(0xffffffffu, pd1, o);
            }
            if (t4 == 0) {
                int r0 = n0 + wid * 32 + mi * 16 + g;
                if (r0 < N_NODES) {
                    g_ssrc[r0 * HEADS + h] = ps0;
                    g_sdst[r0 * HEADS + h] = pd0;
                }
                if (r0 + 8 < N_NODES) {
                    g_ssrc[(r0 + 8) * HEADS + h] = ps1;
                    g_sdst[(r0 + 8) * HEADS + h] = pd1;
                }
            }
        }
    }

    // ---- epilogue -> packed fp16 ----
    __half* packh = (__half*)g_pack;
    #pragma unroll
    for (int mi = 0; mi < 2; mi++) {
        int r0 = n0 + wid * 32 + mi * 16 + g;
        #pragma unroll
        for (int ni = 0; ni < 8; ni++) {
            int col = h * 64 + ni * 8 + 2 * t4;
            int slot = col >> 2;
            int sub = col & 3;
            size_t base0 = ((size_t)r0 * 128 + slot) * 8 + (size_t)mat * 4 + sub;
            size_t base1 = ((size_t)(r0 + 8) * 128 + slot) * 8 + (size_t)mat * 4 + sub;
            if (r0 < N_NODES)
                *(__half2*)(packh + base0) = __floats2half2_rn(c[mi][ni][0], c[mi][ni][1]);
            if (r0 + 8 < N_NODES)
                *(__half2*)(packh + base1) = __floats2half2_rn(c[mi][ni][2], c[mi][ni][3]);
        }
    }
}

// ---------------- helpers ----------------
__device__ __forceinline__ float4 h4_to_f4(uint32_t lo, uint32_t hi) {
    float2 f0 = __half22float2(*(__half2*)&lo);
    float2 f1 = __half22float2(*(__half2*)&hi);
    return make_float4(f0.x, f0.y, f1.x, f1.y);
}

// ---------------- attention (no-max softmax, 4x unrolled, packed fp16) ----------------
__global__ __launch_bounds__(128)
void attn_kernel(const float* __restrict__ a, float* __restrict__ out) {
    int n = blockIdx.x;
    int t = threadIdx.x;
    int h = t >> 4;
    int l = t & 15;

    int e0 = g_off[n];
    int e1 = g_off[n + 1];

    uint4 own = g_pack[(size_t)n * 128 + t];
    float4 hrs = h4_to_f4(own.z, own.w);
    float4 adif = *(const float4*)(a + h * 320 + 128 + l * 4);
    float4 aabs = *(const float4*)(a + h * 320 + 192 + l * 4);
    float4 aprd = *(const float4*)(a + h * 320 + 256 + l * 4);
    float ss = g_ssrc[n * HEADS + h];

    float denom = 0.f;
    float4 acc = make_float4(0.f, 0.f, 0.f, 0.f);

    int i = e0;
    for (; i + 4 <= e1; i += 4) {
        int d0 = g_sorted[i];
        int d1 = g_sorted[i + 1];
        int d2 = g_sorted[i + 2];
        int d3 = g_sorted[i + 3];

        uint4 pk0 = g_pack[(size_t)d0 * 128 + t];
        uint4 pk1 = g_pack[(size_t)d1 * 128 + t];
        uint4 pk2 = g_pack[(size_t)d2 * 128 + t];
        uint4 pk3 = g_pack[(size_t)d3 * 128 + t];
        float sd0 = g_sdst[d0 * HEADS + h];
        float sd1 = g_sdst[d1 * HEADS + h];
        float sd2 = g_sdst[d2 * HEADS + h];
        float sd3 = g_sdst[d3 * HEADS + h];

        float4 he0 = h4_to_f4(pk0.x, pk0.y);
        float4 r0  = h4_to_f4(pk0.z, pk0.w);
        float4 he1 = h4_to_f4(pk1.x, pk1.y);
        float4 r1  = h4_to_f4(pk1.z, pk1.w);
        float4 he2 = h4_to_f4(pk2.x, pk2.y);
        float4 r2  = h4_to_f4(pk2.z, pk2.w);
        float4 he3 = h4_to_f4(pk3.x, pk3.y);
        float4 r3  = h4_to_f4(pk3.z, pk3.w);

        float p0, p1, p2, p3;
        {
            float dx = r0.x - hrs.x, dy = r0.y - hrs.y, dz = r0.z - hrs.z, dw = r0.w - hrs.w;
            p0  = dx * adif.x + fabsf(dx) * aabs.x + hrs.x * r0.x * aprd.x;
            p0 += dy * adif.y + fabsf(dy) * aabs.y + hrs.y * r0.y * aprd.y;
            p0 += dz * adif.z + fabsf(dz) * aabs.z + hrs.z * r0.z * aprd.z;
            p0 += dw * adif.w + fabsf(dw) * aabs.w + hrs.w * r0.w * aprd.w;
        }
        {
            float dx = r1.x - hrs.x, dy = r1.y - hrs.y, dz = r1.z - hrs.z, dw = r1.w - hrs.w;
            p1  = dx * adif.x + fabsf(dx) * aabs.x + hrs.x * r1.x * aprd.x;
            p1 += dy * adif.y + fabsf(dy) * aabs.y + hrs.y * r1.y * aprd.y;
            p1 += dz * adif.z + fabsf(dz) * aabs.z + hrs.z * r1.z * aprd.z;
            p1 += dw * adif.w + fabsf(dw) * aabs.w + hrs.w * r1.w * aprd.w;
        }
        {
            float dx = r2.x - hrs.x, dy = r2.y - hrs.y, dz = r2.z - hrs.z, dw = r2.w - hrs.w;
            p2  = dx * adif.x + fabsf(dx) * aabs.x + hrs.x * r2.x * aprd.x;
            p2 += dy * adif.y + fabsf(dy) * aabs.y + hrs.y * r2.y * aprd.y;
            p2 += dz * adif.z + fabsf(dz) * aabs.z + hrs.z * r2.z * aprd.z;
            p2 += dw * adif.w + fabsf(dw) * aabs.w + hrs.w * r2.w * aprd.w;
        }
        {
            float dx = r3.x - hrs.x, dy = r3.y - hrs.y, dz = r3.z - hrs.z, dw = r3.w - hrs.w;
            p3  = dx * adif.x + fabsf(dx) * aabs.x + hrs.x * r3.x * aprd.x;
            p3 += dy * adif.y + fabsf(dy) * aabs.y + hrs.y * r3.y * aprd.y;
            p3 += dz * adif.z + fabsf(dz) * aabs.z + hrs.z * r3.z * aprd.z;
            p3 += dw * adif.w + fabsf(dw) * aabs.w + hrs.w * r3.w * aprd.w;
        }
        #pragma unroll
        for (int o = 8; o > 0; o >>= 1) {
            p0 += __shfl_xor_sync(0xffffffffu, p0, o);
            p1 += __shfl_xor_sync(0xffffffffu, p1, o);
            p2 += __shfl_xor_sync(0xffffffffu, p2, o);
            p3 += __shfl_xor_sync(0xffffffffu, p3, o);
        }

        float s0 = p0 + ss + sd0;
        float s1 = p1 + ss + sd1;
        float s2 = p2 + ss + sd2;
        float s3 = p3 + ss + sd3;
        float a0 = s0 > 0.f ? s0 : ALPHA_SLOPE * s0;
        float a1 = s1 > 0.f ? s1 : ALPHA_SLOPE * s1;
        float a2 = s2 > 0.f ? s2 : ALPHA_SLOPE * s2;
        float a3 = s3 > 0.f ? s3 : ALPHA_SLOPE * s3;
        float w0 = __expf(a0);
        float w1 = __expf(a1);
        float w2 = __expf(a2);
        float w3 = __expf(a3);

        acc.x += w0 * he0.x + w1 * he1.x + w2 * he2.x + w3 * he3.x;
        acc.y += w0 * he0.y + w1 * he1.y + w2 * he2.y + w3 * he3.y;
        acc.z += w0 * he0.z + w1 * he1.z + w2 * he2.z + w3 * he3.z;
        acc.w += w0 * he0.w + w1 * he1.w + w2 * he2.w + w3 * he3.w;
        denom += w0 + w1 + w2 + w3;
    }
    for (; i < e1; i++) {
        int d0 = g_sorted[i];
        uint4 pk0 = g_pack[(size_t)d0 * 128 + t];
        float sd0 = g_sdst[d0 * HEADS + h];
        float4 he0 = h4_to_f4(pk0.x, pk0.y);
        float4 r0  = h4_to_f4(pk0.z, pk0.w);
        float p0;
        float dx = r0.x - hrs.x, dy = r0.y - hrs.y, dz = r0.z - hrs.z, dw = r0.w - hrs.w;
        p0  = dx * adif.x + fabsf(dx) * aabs.x + hrs.x * r0.x * aprd.x;
        p0 += dy * adif.y + fabsf(dy) * aabs.y + hrs.y * r0.y * aprd.y;
        p0 += dz * adif.z + fabsf(dz) * aabs.z + hrs.z * r0.z * aprd.z;
        p0 += dw * adif.w + fabsf(dw) * aabs.w + hrs.w * r0.w * aprd.w;
        #pragma unroll
        for (int o = 8; o > 0; o >>= 1) p0 += __shfl_xor_sync(0xffffffffu, p0, o);
        float s0 = p0 + ss + sd0;
        float a0 = s0 > 0.f ? s0 : ALPHA_SLOPE * s0;
        float w0 = __expf(a0);
        acc.x += w0 * he0.x;
        acc.y += w0 * he0.y;
        acc.z += w0 * he0.z;
        acc.w += w0 * he0.w;
        denom += w0;
    }

    float inv = 1.f / (denom + EPS_DEN);
    float4 o4 = make_float4(acc.x * inv, acc.y * inv, acc.z * inv, acc.w * inv);
    *(float4*)(out + (size_t)n * HD + t * 4) = o4;
}

// ---------------- launch ----------------
extern "C" void kernel_launch(void* const* d_in, const int* in_sizes, int n_in,
                              void* d_out, int out_size) {
    const float* x = (const float*)d_in[0];
    const void* ei = d_in[1];
    const float* We = (const float*)d_in[2];
    const float* Wr = (const float*)d_in[3];
    const float* a = (const float*)d_in[4];
    float* out = (float*)d_out;

    prep_kernel<<<(N4X + 255) / 256, 256>>>((const float4*)x, (const int*)ei);
    transw_kernel<<<128, 256>>>(We, Wr);
    hist_kernel<<<(N_EDGES + 255) / 256, 256>>>(ei);

    size_t smem_bytes = 2 * BUF_HALFS * sizeof(__half);   // 30720
    cudaFuncSetAttribute(gemm_f16_kernel, cudaFuncAttributeMaxDynamicSharedMemorySize, (int)smem_bytes);
    dim3 ggrid((N_NODES + BM - 1) / BM, 16);
    gemm_f16_kernel<<<ggrid, 128, smem_bytes>>>(a);

    scan1_kernel<<<NB_SCAN, 256>>>();
    scan2_kernel<<<NB_SCAN, 256>>>();
    scatter_kernel<<<(N_EDGES + 255) / 256, 256>>>(ei);

    attn_kernel<<<N_NODES, 128>>>(a, out);
}

// round 17
// speedup vs baseline: 1.0741x; 1.0376x over previous
#include <cuda_runtime.h>
#include <cuda_fp16.h>
#include <math.h>
#include <stdint.h>

#define N_NODES 20000
#define N_EDGES 320000
#define F_IN 512
#define HEADS 8
#define DHEAD 64
#define HD 512
#define ALPHA_SLOPE 0.2f
#define EPS_DEN 1e-16f
#define NB_SCAN ((N_NODES + 255) / 256)   // 79

// ---------------- device scratch ----------------
__device__ uint4  g_pack[N_NODES * 128];            // {he[4] fp16, hr[4] fp16} per slot
__device__ __half g_xh[N_NODES * F_IN];             // fp16 X
__device__ __half g_wh[2 * HEADS * DHEAD * F_IN];   // fp16 W transposed [mat][h][d][f]
__device__ float  g_ssrc[N_NODES * HEADS];
__device__ float  g_sdst[N_NODES * HEADS];
__device__ int    g_cnt[N_NODES];
__device__ int    g_off[N_NODES + 1];
__device__ int    g_cur[N_NODES];
__device__ int    g_sorted[N_EDGES];
__device__ int    g_bsum[NB_SCAN];
__device__ int    g_is64;

#define N4X (N_NODES * F_IN / 4)          // 2,560,000

// ---------------- X -> fp16 (stream A) ----------------
__global__ void xconv_kernel(const float4* __restrict__ x) {
    int i = blockIdx.x * blockDim.x + threadIdx.x;
    if (i < N4X) {
        float4 v = x[i];
        __half2 h0 = __floats2half2_rn(v.x, v.y);
        __half2 h1 = __floats2half2_rn(v.z, v.w);
        uint2 st;
        st.x = *(uint32_t*)&h0;
        st.y = *(uint32_t*)&h1;
        *(uint2*)((__half*)g_xh + (size_t)i * 4) = st;
    }
}

// ---------------- edge prep: zero counters + dtype detect (stream B) ----------------
__global__ void edgeprep_kernel(const int* __restrict__ ei32) {
    int i = blockIdx.x * blockDim.x + threadIdx.x;
    if (i < N_NODES) g_cnt[i] = 0;
    if (i == 0) {
        int odd = 0;
        #pragma unroll 1
        for (int k = 0; k < 64; k++) odd |= ei32[2 * k + 1];
        g_is64 = (odd == 0) ? 1 : 0;
    }
}

// transpose W: [h][f][d] f32 -> [mat][h][d][f] fp16
__global__ void transw_kernel(const float* __restrict__ We, const float* __restrict__ Wr) {
    __shared__ float sm[64][65];
    int bid = blockIdx.x;
    int fc = bid & 7;
    int h = (bid >> 3) & 7;
    int mat = bid >> 6;
    const float* W = (mat == 0) ? We : Wr;
    const float* base = W + (size_t)h * F_IN * DHEAD;
    int t = threadIdx.x;
    #pragma unroll
    for (int j = 0; j < 16; j++) {
        int idx = t + j * 256;
        int fi = idx >> 6, d = idx & 63;
        sm[fi][d] = base[(size_t)(fc * 64 + fi) * DHEAD + d];
    }
    __syncthreads();
    __half2* out = (__half2*)g_wh;
    #pragma unroll
    for (int j = 0; j < 8; j++) {
        int idx = t + j * 256;
        int d = idx >> 5;
        int fp = idx & 31;
        float v0 = sm[fp * 2][d];
        float v1 = sm[fp * 2 + 1][d];
        size_t o = (((size_t)(mat * 8 + h) * 64 + d) * F_IN + fc * 64 + fp * 2) >> 1;
        out[o] = __floats2half2_rn(v0, v1);
    }
}

__device__ __forceinline__ int load_edge(const void* ei, int idx) {
    int v;
    if (g_is64) v = (int)((const long long*)ei)[idx];
    else        v = ((const int*)ei)[idx];
    v = v < 0 ? 0 : (v >= N_NODES ? N_NODES - 1 : v);
    return v;
}

__global__ void hist_kernel(const void* __restrict__ ei) {
    int e = blockIdx.x * blockDim.x + threadIdx.x;
    if (e < N_EDGES) atomicAdd(&g_cnt[load_edge(ei, e)], 1);
}

// ---------------- 2-phase scan ----------------
__global__ void scan1_kernel() {
    __shared__ int ws[8];
    int t = threadIdx.x, lane = t & 31, w = t >> 5;
    int idx = blockIdx.x * 256 + t;
    int v = (idx < N_NODES) ? g_cnt[idx] : 0;
    int x = v;
    #pragma unroll
    for (int o = 16; o > 0; o >>= 1) x += __shfl_xor_sync(0xffffffffu, x, o);
    if (lane == 0) ws[w] = x;
    __syncthreads();
    if (t == 0) {
        int s = 0;
        #pragma unroll
        for (int i = 0; i < 8; i++) s += ws[i];
        g_bsum[blockIdx.x] = s;
    }
}

__global__ void scan2_kernel() {
    __shared__ int ws[8];
    __shared__ int pre;
    int t = threadIdx.x, lane = t & 31, w = t >> 5;
    int idx = blockIdx.x * 256 + t;
    if (t == 0) {
        int s = 0;
        #pragma unroll 1
        for (int i = 0; i < NB_SCAN; i++) {
            if (i == blockIdx.x) break;
            s += g_bsum[i];
        }
        pre = s;
    }
    int v = (idx < N_NODES) ? g_cnt[idx] : 0;
    int x = v;
    #pragma unroll
    for (int o = 1; o < 32; o <<= 1) {
        int y = __shfl_up_sync(0xffffffffu, x, o);
        if (lane >= o) x += y;
    }
    if (lane == 31) ws[w] = x;
    __syncthreads();
    if (t == 0) {
        int s = 0;
        #pragma unroll
        for (int i = 0; i < 8; i++) { int tmp = ws[i]; ws[i] = s; s += tmp; }
    }
    __syncthreads();
    int excl = pre + ws[w] + x - v;
    if (idx < N_NODES) { g_off[idx] = excl; g_cur[idx] = excl; }
    if (blockIdx.x == NB_SCAN - 1 && t == 255) g_off[N_NODES] = excl + v;
}

__global__ void scatter_kernel(const void* __restrict__ ei) {
    int e = blockIdx.x * blockDim.x + threadIdx.x;
    if (e < N_EDGES) {
        int s = load_edge(ei, e);
        int d = load_edge(ei, N_EDGES + e);
        int p = atomicAdd(&g_cur[s], 1);
        if (p >= 0 && p < N_EDGES) g_sorted[p] = d;
    }
}

// ---------------- fp16 tensor-core GEMM (m16n8k16, ldmatrix, 3 CTAs/SM) ----------------
#define BM 128
#define BK 32
#define AS_H 40
#define BS_H 40
#define A_HALFS (BM * AS_H)             // 5120
#define B_HALFS (64 * BS_H)             // 2560
#define BUF_HALFS (A_HALFS + B_HALFS)   // 7680 (15360 B)

__device__ __forceinline__ void cp_async16(uint32_t saddr, const void* gaddr, int sz) {
    asm volatile("cp.async.cg.shared.global [%0], [%1], 16, %2;"
                 :: "r"(saddr), "l"(gaddr), "r"(sz));
}
__device__ __forceinline__ void ldsm_x4(uint32_t& r0, uint32_t& r1, uint32_t& r2, uint32_t& r3,
                                        uint32_t addr) {
    asm volatile("ldmatrix.sync.aligned.m8n8.x4.shared.b16 {%0,%1,%2,%3}, [%4];"
                 : "=r"(r0), "=r"(r1), "=r"(r2), "=r"(r3) : "r"(addr));
}

__global__ __launch_bounds__(128, 3)
void gemm_f16_kernel(const float* __restrict__ av) {
    extern __shared__ __half smh[];
    int tid = threadIdx.x;
    int wid = tid >> 5;
    int lane = tid & 31;
    int g = lane >> 2;
    int t4 = lane & 3;

    int rowA = lane & 15;
    int kA   = (lane >> 4) << 3;
    int colB = ((lane >> 4) << 3) + (lane & 7);
    int kB   = ((lane >> 3) & 1) << 3;

    int n0 = blockIdx.x * BM;
    int hy = blockIdx.y;          // 0..15
    int h = hy & 7;
    int mat = hy >> 3;            // 0=he, 1=hr

    const __half* X = g_xh;
    const __half* Wt = g_wh + (size_t)(mat * 8 + h) * 64 * F_IN;

    uint32_t sm_base = (uint32_t)__cvta_generic_to_shared(smh);

    float c[2][8][4];
    #pragma unroll
    for (int mi = 0; mi < 2; mi++)
        #pragma unroll
        for (int ni = 0; ni < 8; ni++)
            #pragma unroll
            for (int r = 0; r < 4; r++) c[mi][ni][r] = 0.f;

    auto issue = [&](int buf, int f0) {
        uint32_t abase = sm_base + (uint32_t)(buf * BUF_HALFS) * 2u;
        uint32_t bbase = abase + A_HALFS * 2u;
        #pragma unroll
        for (int j = 0; j < 4; j++) {
            int linear = tid + j * 128;
            int row = linear >> 2;
            int q = linear & 3;
            int grow = n0 + row;
            int pred = (grow < N_NODES) ? 16 : 0;
            int clamped = grow < N_NODES ? grow : (N_NODES - 1);
            const void* gp = X + (size_t)clamped * F_IN + f0 + q * 8;
            uint32_t sp = abase + (uint32_t)(row * AS_H + q * 8) * 2u;
            cp_async16(sp, gp, pred);
        }
        #pragma unroll
        for (int j = 0; j < 2; j++) {
            int linear = tid + j * 128;
            int d = linear >> 2;
            int q = linear & 3;
            const void* gp = Wt + (size_t)d * F_IN + f0 + q * 8;
            uint32_t sp = bbase + (uint32_t)(d * BS_H + q * 8) * 2u;
            cp_async16(sp, gp, 16);
        }
        asm volatile("cp.async.commit_group;");
    };

    const int TILES = F_IN / BK;   // 16
    issue(0, 0);

    for (int ti = 0; ti < TILES; ti++) {
        if (ti + 1 < TILES) {
            issue((ti + 1) & 1, (ti + 1) * BK);
            asm volatile("cp.async.wait_group 1;");
        } else {
            asm volatile("cp.async.wait_group 0;");
        }
        __syncthreads();

        uint32_t abyte = sm_base + (uint32_t)((ti & 1) * BUF_HALFS) * 2u;
        uint32_t bbyte = abyte + A_HALFS * 2u;

        #pragma unroll
        for (int ks = 0; ks < 2; ks++) {
            int k0 = ks * 16;
            uint32_t a[2][4], b[8][2];
            #pragma unroll
            for (int mi = 0; mi < 2; mi++) {
                uint32_t addr = abyte +
                    (uint32_t)((wid * 32 + mi * 16 + rowA) * AS_H + k0 + kA) * 2u;
                ldsm_x4(a[mi][0], a[mi][1], a[mi][2], a[mi][3], addr);
            }
            #pragma unroll
            for (int p = 0; p < 4; p++) {
                uint32_t addr = bbyte +
                    (uint32_t)((p * 16 + colB) * BS_H + k0 + kB) * 2u;
                ldsm_x4(b[2 * p][0], b[2 * p][1], b[2 * p + 1][0], b[2 * p + 1][1], addr);
            }
            #pragma unroll
            for (int mi = 0; mi < 2; mi++)
                #pragma unroll
                for (int ni = 0; ni < 8; ni++) {
                    asm volatile(
                        "mma.sync.aligned.m16n8k16.row.col.f32.f16.f16.f32 "
                        "{%0,%1,%2,%3}, {%4,%5,%6,%7}, {%8,%9}, {%0,%1,%2,%3};"
                        : "+f"(c[mi][ni][0]), "+f"(c[mi][ni][1]),
                          "+f"(c[mi][ni][2]), "+f"(c[mi][ni][3])
                        : "r"(a[mi][0]), "r"(a[mi][1]), "r"(a[mi][2]), "r"(a[mi][3]),
                          "r"(b[ni][0]), "r"(b[ni][1]));
                }
        }
        __syncthreads();
    }

    // ---- fused s-dots (mat==0): ssrc/sdst from fp32 accumulators ----
    if (mat == 0) {
        float as0[8], as1[8], ad0[8], ad1[8];
        #pragma unroll
        for (int ni = 0; ni < 8; ni++) {
            int d0 = ni * 8 + 2 * t4;
            as0[ni] = av[h * 320 + d0];
            as1[ni] = av[h * 320 + d0 + 1];
            ad0[ni] = av[h * 320 + 64 + d0];
            ad1[ni] = av[h * 320 + 64 + d0 + 1];
        }
        #pragma unroll
        for (int mi = 0; mi < 2; mi++) {
            float ps0 = 0.f, ps1 = 0.f, pd0 = 0.f, pd1 = 0.f;
            #pragma unroll
            for (int ni = 0; ni < 8; ni++) {
                ps0 += c[mi][ni][0] * as0[ni] + c[mi][ni][1] * as1[ni];
                ps1 += c[mi][ni][2] * as0[ni] + c[mi][ni][3] * as1[ni];
                pd0 += c[mi][ni][0] * ad0[ni] + c[mi][ni][1] * ad1[ni];
                pd1 += c[mi][ni][2] * ad0[ni] + c[mi][ni][3] * ad1[ni];
            }
            #pragma unroll
            for (int o = 1; o <= 2; o <<= 1) {
                ps0 += __shfl_xor_sync(0xffffffffu, ps0, o);
                ps1 += __shfl_xor_sync(0xffffffffu, ps1, o);
                pd0 += __shfl_xor_sync(0xffffffffu, pd0, o);
                pd1 += __shfl_xor_sync(0xffffffffu, pd1, o);
            }
            if (t4 == 0) {
                int r0 = n0 + wid * 32 + mi * 16 + g;
                if (r0 < N_NODES) {
                    g_ssrc[r0 * HEADS + h] = ps0;
                    g_sdst[r0 * HEADS + h] = pd0;
                }
                if (r0 + 8 < N_NODES) {
                    g_ssrc[(r0 + 8) * HEADS + h] = ps1;
                    g_sdst[(r0 + 8) * HEADS + h] = pd1;
                }
            }
        }
    }

    // ---- epilogue -> packed fp16 ----
    __half* packh = (__half*)g_pack;
    #pragma unroll
    for (int mi = 0; mi < 2; mi++) {
        int r0 = n0 + wid * 32 + mi * 16 + g;
        #pragma unroll
        for (int ni = 0; ni < 8; ni++) {
            int col = h * 64 + ni * 8 + 2 * t4;
            int slot = col >> 2;
            int sub = col & 3;
            size_t base0 = ((size_t)r0 * 128 + slot) * 8 + (size_t)mat * 4 + sub;
            size_t base1 = ((size_t)(r0 + 8) * 128 + slot) * 8 + (size_t)mat * 4 + sub;
            if (r0 < N_NODES)
                *(__half2*)(packh + base0) = __floats2half2_rn(c[mi][ni][0], c[mi][ni][1]);
            if (r0 + 8 < N_NODES)
                *(__half2*)(packh + base1) = __floats2half2_rn(c[mi][ni][2], c[mi][ni][3]);
        }
    }
}

// ---------------- helpers ----------------
__device__ __forceinline__ float4 h4_to_f4(uint32_t lo, uint32_t hi) {
    float2 f0 = __half22float2(*(__half2*)&lo);
    float2 f1 = __half22float2(*(__half2*)&hi);
    return make_float4(f0.x, f0.y, f1.x, f1.y);
}

// ---------------- attention (no-max softmax, 4x unrolled, packed fp16) ----------------
__global__ __launch_bounds__(128)
void attn_kernel(const float* __restrict__ a, float* __restrict__ out) {
    int n = blockIdx.x;
    int t = threadIdx.x;
    int h = t >> 4;
    int l = t & 15;

    int e0 = g_off[n];
    int e1 = g_off[n + 1];

    uint4 own = g_pack[(size_t)n * 128 + t];
    float4 hrs = h4_to_f4(own.z, own.w);
    float4 adif = *(const float4*)(a + h * 320 + 128 + l * 4);
    float4 aabs = *(const float4*)(a + h * 320 + 192 + l * 4);
    float4 aprd = *(const float4*)(a + h * 320 + 256 + l * 4);
    float ss = g_ssrc[n * HEADS + h];

    float denom = 0.f;
    float4 acc = make_float4(0.f, 0.f, 0.f, 0.f);

    int i = e0;
    for (; i + 4 <= e1; i += 4) {
        int d0 = g_sorted[i];
        int d1 = g_sorted[i + 1];
        int d2 = g_sorted[i + 2];
        int d3 = g_sorted[i + 3];

        uint4 pk0 = g_pack[(size_t)d0 * 128 + t];
        uint4 pk1 = g_pack[(size_t)d1 * 128 + t];
        uint4 pk2 = g_pack[(size_t)d2 * 128 + t];
        uint4 pk3 = g_pack[(size_t)d3 * 128 + t];
        float sd0 = g_sdst[d0 * HEADS + h];
        float sd1 = g_sdst[d1 * HEADS + h];
        float sd2 = g_sdst[d2 * HEADS + h];
        float sd3 = g_sdst[d3 * HEADS + h];

        float4 he0 = h4_to_f4(pk0.x, pk0.y);
        float4 r0  = h4_to_f4(pk0.z, pk0.w);
        float4 he1 = h4_to_f4(pk1.x, pk1.y);
        float4 r1  = h4_to_f4(pk1.z, pk1.w);
        float4 he2 = h4_to_f4(pk2.x, pk2.y);
        float4 r2  = h4_to_f4(pk2.z, pk2.w);
        float4 he3 = h4_to_f4(pk3.x, pk3.y);
        float4 r3  = h4_to_f4(pk3.z, pk3.w);

        float p0, p1, p2, p3;
        {
            float dx = r0.x - hrs.x, dy = r0.y - hrs.y, dz = r0.z - hrs.z, dw = r0.w - hrs.w;
            p0  = dx * adif.x + fabsf(dx) * aabs.x + hrs.x * r0.x * aprd.x;
            p0 += dy * adif.y + fabsf(dy) * aabs.y + hrs.y * r0.y * aprd.y;
            p0 += dz * adif.z + fabsf(dz) * aabs.z + hrs.z * r0.z * aprd.z;
            p0 += dw * adif.w + fabsf(dw) * aabs.w + hrs.w * r0.w * aprd.w;
        }
        {
            float dx = r1.x - hrs.x, dy = r1.y - hrs.y, dz = r1.z - hrs.z, dw = r1.w - hrs.w;
            p1  = dx * adif.x + fabsf(dx) * aabs.x + hrs.x * r1.x * aprd.x;
            p1 += dy * adif.y + fabsf(dy) * aabs.y + hrs.y * r1.y * aprd.y;
            p1 += dz * adif.z + fabsf(dz) * aabs.z + hrs.z * r1.z * aprd.z;
            p1 += dw * adif.w + fabsf(dw) * aabs.w + hrs.w * r1.w * aprd.w;
        }
        {
            float dx = r2.x - hrs.x, dy = r2.y - hrs.y, dz = r2.z - hrs.z, dw = r2.w - hrs.w;
            p2  = dx * adif.x + fabsf(dx) * aabs.x + hrs.x * r2.x * aprd.x;
            p2 += dy * adif.y + fabsf(dy) * aabs.y + hrs.y * r2.y * aprd.y;
            p2 += dz * adif.z + fabsf(dz) * aabs.z + hrs.z * r2.z * aprd.z;
            p2 += dw * adif.w + fabsf(dw) * aabs.w + hrs.w * r2.w * aprd.w;
        }
        {
            float dx = r3.x - hrs.x, dy = r3.y - hrs.y, dz = r3.z - hrs.z, dw = r3.w - hrs.w;
            p3  = dx * adif.x + fabsf(dx) * aabs.x + hrs.x * r3.x * aprd.x;
            p3 += dy * adif.y + fabsf(dy) * aabs.y + hrs.y * r3.y * aprd.y;
            p3 += dz * adif.z + fabsf(dz) * aabs.z + hrs.z * r3.z * aprd.z;
            p3 += dw * adif.w + fabsf(dw) * aabs.w + hrs.w * r3.w * aprd.w;
        }
        #pragma unroll
        for (int o = 8; o > 0; o >>= 1) {
            p0 += __shfl_xor_sync(0xffffffffu, p0, o);
            p1 += __shfl_xor_sync(0xffffffffu, p1, o);
            p2 += __shfl_xor_sync(0xffffffffu, p2, o);
            p3 += __shfl_xor_sync(0xffffffffu, p3, o);
        }

        float s0 = p0 + ss + sd0;
        float s1 = p1 + ss + sd1;
        float s2 = p2 + ss + sd2;
        float s3 = p3 + ss + sd3;
        float a0 = s0 > 0.f ? s0 : ALPHA_SLOPE * s0;
        float a1 = s1 > 0.f ? s1 : ALPHA_SLOPE * s1;
        float a2 = s2 > 0.f ? s2 : ALPHA_SLOPE * s2;
        float a3 = s3 > 0.f ? s3 : ALPHA_SLOPE * s3;
        float w0 = __expf(a0);
        float w1 = __expf(a1);
        float w2 = __expf(a2);
        float w3 = __expf(a3);

        acc.x += w0 * he0.x + w1 * he1.x + w2 * he2.x + w3 * he3.x;
        acc.y += w0 * he0.y + w1 * he1.y + w2 * he2.y + w3 * he3.y;
        acc.z += w0 * he0.z + w1 * he1.z + w2 * he2.z + w3 * he3.z;
        acc.w += w0 * he0.w + w1 * he1.w + w2 * he2.w + w3 * he3.w;
        denom += w0 + w1 + w2 + w3;
    }
    for (; i < e1; i++) {
        int d0 = g_sorted[i];
        uint4 pk0 = g_pack[(size_t)d0 * 128 + t];
        float sd0 = g_sdst[d0 * HEADS + h];
        float4 he0 = h4_to_f4(pk0.x, pk0.y);
        float4 r0  = h4_to_f4(pk0.z, pk0.w);
        float p0;
        float dx = r0.x - hrs.x, dy = r0.y - hrs.y, dz = r0.z - hrs.z, dw = r0.w - hrs.w;
        p0  = dx * adif.x + fabsf(dx) * aabs.x + hrs.x * r0.x * aprd.x;
        p0 += dy * adif.y + fabsf(dy) * aabs.y + hrs.y * r0.y * aprd.y;
        p0 += dz * adif.z + fabsf(dz) * aabs.z + hrs.z * r0.z * aprd.z;
        p0 += dw * adif.w + fabsf(dw) * aabs.w + hrs.w * r0.w * aprd.w;
        #pragma unroll
        for (int o = 8; o > 0; o >>= 1) p0 += __shfl_xor_sync(0xffffffffu, p0, o);
        float s0 = p0 + ss + sd0;
        float a0 = s0 > 0.f ? s0 : ALPHA_SLOPE * s0;
        float w0 = __expf(a0);
        acc.x += w0 * he0.x;
        acc.y += w0 * he0.y;
        acc.z += w0 * he0.z;
        acc.w += w0 * he0.w;
        denom += w0;
    }

    float inv = 1.f / (denom + EPS_DEN);
    float4 o4 = make_float4(acc.x * inv, acc.y * inv, acc.z * inv, acc.w * inv);
    *(float4*)(out + (size_t)n * HD + t * 4) = o4;
}

// ---------------- launch: fork-join overlap of edge chain with GEMM chain ----------------
extern "C" void kernel_launch(void* const* d_in, const int* in_sizes, int n_in,
                              void* d_out, int out_size) {
    const float* x = (const float*)d_in[0];
    const void* ei = d_in[1];
    const float* We = (const float*)d_in[2];
    const float* Wr = (const float*)d_in[3];
    const float* a = (const float*)d_in[4];
    float* out = (float*)d_out;

    static cudaStream_t s_b = nullptr;
    static cudaEvent_t ev_fork = nullptr, ev_join = nullptr;
    if (s_b == nullptr) {
        cudaStreamCreateWithFlags(&s_b, cudaStreamNonBlocking);
        cudaEventCreateWithFlags(&ev_fork, cudaEventDisableTiming);
        cudaEventCreateWithFlags(&ev_join, cudaEventDisableTiming);
    }

    // fork: edge chain on stream B
    cudaEventRecord(ev_fork, 0);
    cudaStreamWaitEvent(s_b, ev_fork, 0);
    edgeprep_kernel<<<(N_NODES + 255) / 256, 256, 0, s_b>>>((const int*)ei);
    hist_kernel<<<(N_EDGES + 255) / 256, 256, 0, s_b>>>(ei);
    scan1_kernel<<<NB_SCAN, 256, 0, s_b>>>();
    scan2_kernel<<<NB_SCAN, 256, 0, s_b>>>();
    scatter_kernel<<<(N_EDGES + 255) / 256, 256, 0, s_b>>>(ei);
    cudaEventRecord(ev_join, s_b);

    // main chain: projections
    xconv_kernel<<<(N4X + 255) / 256, 256>>>((const float4*)x);
    transw_kernel<<<128, 256>>>(We, Wr);

    size_t smem_bytes = 2 * BUF_HALFS * sizeof(__half);   // 30720
    cudaFuncSetAttribute(gemm_f16_kernel, cudaFuncAttributeMaxDynamicSharedMemorySize, (int)smem_bytes);
    dim3 ggrid((N_NODES + BM - 1) / BM, 16);
    gemm_f16_kernel<<<ggrid, 128, smem_bytes>>>(a);

    // join: attn needs GEMM (stream 0) + scatter (stream B)
    cudaStreamWaitEvent(0, ev_join, 0);
    attn_kernel<<<N_NODES, 128>>>(a, out);
}